// round 1
// baseline (speedup 1.0000x reference)
#include <cuda_runtime.h>
#include <math.h>

#define NOBJ   256
#define CCLS   151
#define DH     512
#define NC     (NOBJ*CCLS)          // 38656
#define KFULL  (CCLS*DH)            // 77312
#define TSTEPS 3
#define KSPLIT 38
#define KCHUNK 2048

// ---------------- device scratch (allocation-free: __device__ globals) -------
__device__ float g_h  [(size_t)NC*DH];     // hidden state [NC, D]
__device__ float g_zv [(size_t)NC*DH];     // z gate
__device__ float g_rh [(size_t)NC*DH];     // r*h  (later reused as relu-out buffer)
__device__ float g_row[NOBJ*DH];           // per-object sum over classes
__device__ float g_tot[DH];                // global sum
__device__ float g_s  [NOBJ*DH];           // s[n,d] = m*(TOT - row)
__device__ float g_avW[3*NOBJ*DH];         // s @ Weff_q.T + b_qw   (q = 3,4,5)
__device__ float g_Weff[3*DH*DH];          // folded w3w/w4w/w5w (both halves summed)
__device__ float g_P  [NOBJ*DH];           // input @ wo[:,D:].T
__device__ float g_part[(size_t)KSPLIT*NOBJ*CCLS]; // split-K partials

// ---------------- small helper kernels --------------------------------------
__global__ void k_init(const float* __restrict__ inp) {
    int row = blockIdx.x;            // 0..NC-1
    int d   = threadIdx.x;           // 0..511
    int n   = row / CCLS;
    g_h[(size_t)row*DH + d] = inp[n*DH + d];
}

__global__ void k_fold(const float* __restrict__ w3w,
                       const float* __restrict__ w4w,
                       const float* __restrict__ w5w) {
    int i = blockIdx.x*blockDim.x + threadIdx.x;
    if (i >= 3*DH*DH) return;
    int q = i / (DH*DH);
    int r = i % (DH*DH);
    int o = r / DH, c = r % DH;
    const float* w = (q==0) ? w3w : (q==1) ? w4w : w5w;
    g_Weff[i] = w[o*2*DH + c] + w[o*2*DH + DH + c];
}

__global__ void k_rowsum() {
    int n = blockIdx.x, d = threadIdx.x;
    const float* p = &g_h[(size_t)n*CCLS*DH + d];
    float s = 0.f;
    for (int c = 0; c < CCLS; c++) s += p[(size_t)c*DH];
    g_row[n*DH + d] = s;
}

__global__ void k_tot() {
    int d = threadIdx.x;
    float s = 0.f;
    for (int n = 0; n < NOBJ; n++) s += g_row[n*DH + d];
    g_tot[d] = s;
}

__global__ void k_s(const float* __restrict__ matrix) {
    float m = matrix[0];             // uniform prior matrix (ones/C)
    int n = blockIdx.x, d = threadIdx.x;
    g_s[n*DH + d] = m * (g_tot[d] - g_row[n*DH + d]);
}

// ---------------- generic fused GEMM ----------------------------------------
// C[r,c] = sum_k A[r,k]*B[c,k].  M%128==0, N==512 (tiles of 128), K%16==0.
enum { EPI_STORE=0, EPI_BIAS=1, EPI_GRU1=2, EPI_GRU2=3, EPI_RELU=4 };

struct EpiArgs {
    const float* bias;
    const float* a0;
    const float* a1;
    const float* a2;
    float*       o0;
    float*       o1;
};

__device__ __forceinline__ float sigf(float x) { return 1.f/(1.f + expf(-x)); }

template<int EPI>
__global__ void __launch_bounds__(256)
k_gemm(const float* __restrict__ A, int lda,
       const float* __restrict__ B, int ldb,
       float* __restrict__ Cp, int K, EpiArgs ea)
{
    __shared__ float As[16][132];
    __shared__ float Bs[16][132];
    const int row0 = blockIdx.y*128;
    const int col0 = blockIdx.x*128;
    const int tid  = threadIdx.x;
    const int tx   = tid & 15, ty = tid >> 4;

    float acc[8][8];
    #pragma unroll
    for (int i = 0; i < 8; i++)
        #pragma unroll
        for (int j = 0; j < 8; j++) acc[i][j] = 0.f;

    for (int kt = 0; kt < K; kt += 16) {
        #pragma unroll
        for (int l = 0; l < 2; l++) {
            int f  = tid + l*256;
            int r  = f >> 2;
            int kq = (f & 3) << 2;
            float4 av = *(const float4*)(A + (size_t)(row0+r)*lda + kt + kq);
            As[kq+0][r]=av.x; As[kq+1][r]=av.y; As[kq+2][r]=av.z; As[kq+3][r]=av.w;
            float4 bv = *(const float4*)(B + (size_t)(col0+r)*ldb + kt + kq);
            Bs[kq+0][r]=bv.x; Bs[kq+1][r]=bv.y; Bs[kq+2][r]=bv.z; Bs[kq+3][r]=bv.w;
        }
        __syncthreads();
        #pragma unroll
        for (int k = 0; k < 16; k++) {
            float a[8], b[8];
            *(float4*)&a[0] = *(const float4*)&As[k][ty*8];
            *(float4*)&a[4] = *(const float4*)&As[k][ty*8+4];
            *(float4*)&b[0] = *(const float4*)&Bs[k][tx*8];
            *(float4*)&b[4] = *(const float4*)&Bs[k][tx*8+4];
            #pragma unroll
            for (int i = 0; i < 8; i++)
                #pragma unroll
                for (int j = 0; j < 8; j++) acc[i][j] += a[i]*b[j];
        }
        __syncthreads();
    }

    #pragma unroll
    for (int i = 0; i < 8; i++) {
        int r = row0 + ty*8 + i;
        int n = r / CCLS;
        #pragma unroll
        for (int j = 0; j < 8; j++) {
            int c = col0 + tx*8 + j;
            float v = acc[i][j];
            if (EPI == EPI_STORE) {
                Cp[(size_t)r*DH + c] = v;
            } else if (EPI == EPI_BIAS) {
                Cp[(size_t)r*DH + c] = v + ea.bias[c];
            } else if (EPI == EPI_GRU1) {
                float u  = v + ea.bias[c];
                float z  = sigf(ea.a0[n*DH + c] + u);   // avW3
                float rv = sigf(ea.a1[n*DH + c] + u);   // avW4
                size_t idx = (size_t)r*DH + c;
                ea.o0[idx] = z;                          // g_zv
                ea.o1[idx] = rv * ea.a2[idx];            // g_rh = rv*h
            } else if (EPI == EPI_GRU2) {
                size_t idx = (size_t)r*DH + c;
                float hv = tanhf(v + ea.bias[c] + ea.a0[n*DH + c]); // avW5
                float z  = ea.a1[idx];                   // zv
                ea.o0[idx] = (1.f - z)*ea.a2[idx] + z*hv; // new h
            } else { // EPI_RELU
                size_t idx = (size_t)r*DH + c;
                float x = v + ea.bias[c] + ea.a0[n*DH + c]; // + P[n,:]
                ea.o0[idx] = x > 0.f ? x : 0.f;
            }
        }
    }
}

// ---------------- final classifier: [256,77312] x [77312,151], split-K ------
__global__ void __launch_bounds__(256)
k_cls(const float* __restrict__ Afull, const float* __restrict__ wc)
{
    __shared__ float As[16][68];
    __shared__ float Bs[16][161];
    const int ks    = blockIdx.x;
    const int ntile = blockIdx.y * 64;
    const int tid   = threadIdx.x;
    const int tm    = tid >> 5;   // 0..7
    const int tc    = tid & 31;   // 0..31
    const int k0    = ks*KCHUNK;
    const int k1    = min(k0 + KCHUNK, KFULL);

    float acc[8][5];
    #pragma unroll
    for (int i = 0; i < 8; i++)
        #pragma unroll
        for (int q = 0; q < 5; q++) acc[i][q] = 0.f;

    for (int kt = k0; kt < k1; kt += 16) {
        {   // A tile: 64 rows x 16 k -> 256 float4, 1 per thread
            int r  = tid >> 2;
            int kq = (tid & 3) << 2;
            float4 av = *(const float4*)(Afull + (size_t)(ntile + r)*KFULL + kt + kq);
            As[kq+0][r]=av.x; As[kq+1][r]=av.y; As[kq+2][r]=av.z; As[kq+3][r]=av.w;
        }
        // B tile: 160 rows x 16 k (rows >= 151 zero-filled)
        for (int f = tid; f < 640; f += 256) {
            int r  = f >> 2;
            int kq = (f & 3) << 2;
            float4 bv = make_float4(0.f,0.f,0.f,0.f);
            if (r < CCLS) bv = *(const float4*)(wc + (size_t)r*KFULL + kt + kq);
            Bs[kq+0][r]=bv.x; Bs[kq+1][r]=bv.y; Bs[kq+2][r]=bv.z; Bs[kq+3][r]=bv.w;
        }
        __syncthreads();
        #pragma unroll
        for (int k = 0; k < 16; k++) {
            float a[8];
            *(float4*)&a[0] = *(const float4*)&As[k][tm*8];
            *(float4*)&a[4] = *(const float4*)&As[k][tm*8+4];
            float b[5];
            #pragma unroll
            for (int q = 0; q < 5; q++) b[q] = Bs[k][tc + 32*q];
            #pragma unroll
            for (int i = 0; i < 8; i++)
                #pragma unroll
                for (int q = 0; q < 5; q++) acc[i][q] += a[i]*b[q];
        }
        __syncthreads();
    }

    float* dst = g_part + (size_t)ks*NOBJ*CCLS;
    #pragma unroll
    for (int i = 0; i < 8; i++) {
        int n = ntile + tm*8 + i;
        #pragma unroll
        for (int q = 0; q < 5; q++) {
            int c = tc + 32*q;
            if (c < CCLS) dst[n*CCLS + c] = acc[i][q];
        }
    }
}

__global__ void k_reduce(const float* __restrict__ bc, float* __restrict__ out) {
    int i = blockIdx.x*blockDim.x + threadIdx.x;
    if (i >= NOBJ*CCLS) return;
    int c = i % CCLS;
    float s = bc[c];
    #pragma unroll 1
    for (int ks = 0; ks < KSPLIT; ks++) s += g_part[(size_t)ks*NOBJ*CCLS + i];
    out[i] = s;
}

// ---------------- host ------------------------------------------------------
extern "C" void kernel_launch(void* const* d_in, const int* in_sizes, int n_in,
                              void* d_out, int out_size)
{
    const float* input  = (const float*)d_in[0];
    const float* matrix = (const float*)d_in[1];
    const float* w3w = (const float*)d_in[2];  const float* b3w = (const float*)d_in[3];
    const float* w3u = (const float*)d_in[4];  const float* b3u = (const float*)d_in[5];
    const float* w4w = (const float*)d_in[6];  const float* b4w = (const float*)d_in[7];
    /* w4u=d_in[8], b4u=d_in[9] unused (reference faithfully reuses w3u/b3u) */
    const float* w5w = (const float*)d_in[10]; const float* b5w = (const float*)d_in[11];
    const float* w5u = (const float*)d_in[12]; const float* b5u = (const float*)d_in[13];
    const float* wo  = (const float*)d_in[14]; const float* bo  = (const float*)d_in[15];
    const float* wc  = (const float*)d_in[16]; const float* bc  = (const float*)d_in[17];
    float* out = (float*)d_out;

    float *ph, *pzv, *prh, *ps, *pavW, *pWeff, *pP;
    cudaGetSymbolAddress((void**)&ph,    g_h);
    cudaGetSymbolAddress((void**)&pzv,   g_zv);
    cudaGetSymbolAddress((void**)&prh,   g_rh);
    cudaGetSymbolAddress((void**)&ps,    g_s);
    cudaGetSymbolAddress((void**)&pavW,  g_avW);
    cudaGetSymbolAddress((void**)&pWeff, g_Weff);
    cudaGetSymbolAddress((void**)&pP,    g_P);

    EpiArgs ez = {nullptr,nullptr,nullptr,nullptr,nullptr,nullptr};

    // init hidden + fold gate weights + precompute P = input @ wo[:,D:].T
    k_init<<<NC, DH>>>(input);
    k_fold<<<(3*DH*DH + 255)/256, 256>>>(w3w, w4w, w5w);
    k_gemm<EPI_STORE><<<dim3(4, 2), 256>>>(input, DH, wo + DH, 2*DH, pP, DH, ez);

    const dim3 gSmall(4, 2);      // 256 x 512
    const dim3 gBig(4, NC/128);   // 38656 x 512

    for (int t = 0; t < TSTEPS; t++) {
        k_rowsum<<<NOBJ, DH>>>();
        k_tot<<<1, DH>>>();
        k_s<<<NOBJ, DH>>>(matrix);

        EpiArgs e3 = {b3w,nullptr,nullptr,nullptr,nullptr,nullptr};
        k_gemm<EPI_BIAS><<<gSmall, 256>>>(ps, DH, pWeff + 0*DH*DH, DH, pavW + 0*NOBJ*DH, DH, e3);
        EpiArgs e4 = {b4w,nullptr,nullptr,nullptr,nullptr,nullptr};
        k_gemm<EPI_BIAS><<<gSmall, 256>>>(ps, DH, pWeff + 1*DH*DH, DH, pavW + 1*NOBJ*DH, DH, e4);
        EpiArgs e5 = {b5w,nullptr,nullptr,nullptr,nullptr,nullptr};
        k_gemm<EPI_BIAS><<<gSmall, 256>>>(ps, DH, pWeff + 2*DH*DH, DH, pavW + 2*NOBJ*DH, DH, e5);

        // U = h @ w3u.T ; epilogue -> zv, r*h
        EpiArgs eg1 = {b3u, pavW + 0*NOBJ*DH, pavW + 1*NOBJ*DH, ph, pzv, prh};
        k_gemm<EPI_GRU1><<<gBig, 256>>>(ph, DH, w3u, DH, nullptr, DH, eg1);

        // V = (r*h) @ w5u.T ; epilogue -> h = (1-z)h + z*tanh(...)
        EpiArgs eg2 = {b5u, pavW + 2*NOBJ*DH, pzv, ph, ph, nullptr};
        k_gemm<EPI_GRU2><<<gBig, 256>>>(prh, DH, w5u, DH, nullptr, DH, eg2);
    }

    // out = relu(h @ wo[:,:D].T + P + bo)  -> g_rh (reused as output buffer)
    EpiArgs er = {bo, pP, nullptr, nullptr, prh, nullptr};
    k_gemm<EPI_RELU><<<gBig, 256>>>(ph, DH, wo, 2*DH, nullptr, DH, er);

    // classifier: split-K partials then deterministic reduce (+bc)
    k_cls<<<dim3(KSPLIT, NOBJ/64), 256>>>(prh, wc);
    k_reduce<<<(NOBJ*CCLS + 255)/256, 256>>>(bc, out);
}